// round 15
// baseline (speedup 1.0000x reference)
#include <cuda_runtime.h>
#include <math.h>

#define NHEAD 32
#define DDIM  128
#define KVLEN 32768
#define PAGE  16
#define NPAGE 2048
#define TOPK  256
#define NSEL  (TOPK * PAGE)          /* 4096 selected tokens per head */
#define HDIM  4096
#define SCALE 0.08838834764831845f   /* 1/sqrt(128) */

// ---------------- scratch (device globals; no allocations allowed) ----------
// Per-rowgroup GEMV partials: written with plain stores every run (no init).
__device__ float g_qp[8][HDIM];
__device__ float g_kp[8][HDIM];
__device__ float g_vp[8][HDIM];
__device__ float g_sall[NHEAD * KVLEN];  // all scores, scaled (4 MB)
__device__ float g_est[NHEAD * NPAGE];   // page estimates
__device__ float g_pmax[NHEAD * NPAGE];  // per-page score max (for softmax m)
__device__ int   g_selp[NHEAD * TOPK];   // selected page ids
__device__ float g_m[NHEAD];             // softmax shift (global score max)
__device__ float g_z[NHEAD];             // running Z (unnormalized)
__device__ float g_o[NHEAD * DDIM];      // UNNORMALIZED attention output
__device__ int   g_qdone = 0;            // #Q-GEMV blocks finished; k_out resets

// ---------------- 1: FUSED QKV GEMV + page scan ------------------------------
// blocks 0..767  : GEMV partials for Wq (0..255), Wk (256..511), Wv (512..767).
// blocks 768..8959: scan; waits for all 256 Q blocks, then proceeds.
__global__ void __launch_bounds__(256) k_gemvscan(const float* __restrict__ kc,
                                                  const float* __restrict__ x,
                                                  const float* __restrict__ Wq,
                                                  const float* __restrict__ Wk,
                                                  const float* __restrict__ Wv) {
    if (blockIdx.x < 768) {
        int b  = blockIdx.x;
        int m  = b >> 8;           // 0 -> Wq, 1 -> Wk, 2 -> Wv
        int r  = b & 255;
        int cg = r & 31;
        int rg = r >> 5;
        const float* W = (m == 0) ? Wq : (m == 1) ? Wk : Wv;

        int lane = threadIdx.x & 31;
        int wrp  = threadIdx.x >> 5;   // 8 warps, 64 rows each

        __shared__ float xs[512];
        __shared__ float part[8][128]; // per-warp partials for the 128 cols
        for (int i = threadIdx.x; i < 512; i += 256) xs[i] = x[rg * 512 + i];
        __syncthreads();

        int col4 = cg * 32 + lane;
        long i0  = (long)rg * 512 + wrp * 64;
        const float4* W4 = (const float4*)W;

        float4 acc = make_float4(0.f, 0.f, 0.f, 0.f);
#pragma unroll 8
        for (int i = 0; i < 64; i++) {
            float  xv = xs[wrp * 64 + i];
            float4 wv = __ldg(&W4[(i0 + i) * 1024 + col4]);
            acc.x += xv * wv.x; acc.y += xv * wv.y;
            acc.z += xv * wv.z; acc.w += xv * wv.w;
        }
        // combine the 8 warps' partials in shared, then ONE plain store
        ((float4*)part[wrp])[lane] = acc;
        __syncthreads();
        if (wrp == 0) {
            float4 s = make_float4(0.f, 0.f, 0.f, 0.f);
#pragma unroll
            for (int w2 = 0; w2 < 8; w2++) {
                float4 p = ((float4*)part[w2])[lane];
                s.x += p.x; s.y += p.y; s.z += p.z; s.w += p.w;
            }
            float* dstbase = (m == 0) ? g_qp[rg] : (m == 1) ? g_kp[rg] : g_vp[rg];
            *(float4*)&dstbase[col4 * 4] = s;
        }
        if (m == 0) {
            __threadfence();
            __syncthreads();
            if (threadIdx.x == 0) atomicAdd(&g_qdone, 1);
        }
        return;
    }

    // ---- scan: one warp per (page, head) --------------------------------
    __shared__ __align__(16) float scos[64], ssin[64];
    // trig table per block (overlaps with the spin below)
    if (threadIdx.x < 64) {
        float inv = (float)pow(10000.0, -(double)threadIdx.x / 64.0);
        float ang = 32768.0f * inv;
        float s, c;
        sincosf(ang, &s, &c);
        scos[threadIdx.x] = c;
        ssin[threadIdx.x] = s;
    }
    if (threadIdx.x == 0) {
        while (atomicAdd(&g_qdone, 0) < 256) __nanosleep(32);
    }
    __syncthreads();

    int g    = (blockIdx.x - 768) * 8 + (threadIdx.x >> 5);
    int lane = threadIdx.x & 31;
    int p = g >> 5, h = g & 31;

    // q = sum of 8 rowgroup partials (L2-resident)
    float4 q4 = make_float4(0.f, 0.f, 0.f, 0.f);
#pragma unroll
    for (int rg = 0; rg < 8; rg++) {
        float4 qp = ((const float4*)g_qp[rg])[h * 32 + lane];
        q4.x += qp.x; q4.y += qp.y; q4.z += qp.z; q4.w += qp.w;
    }
    // RoPE: dims i<64 pair with i+64; partner lives in lane^16
    float4 pq;
    pq.x = __shfl_xor_sync(0xffffffffu, q4.x, 16);
    pq.y = __shfl_xor_sync(0xffffffffu, q4.y, 16);
    pq.z = __shfl_xor_sync(0xffffffffu, q4.z, 16);
    pq.w = __shfl_xor_sync(0xffffffffu, q4.w, 16);
    int ai = (lane & 15) * 4;
    float4 cc = *(const float4*)&scos[ai];
    float4 ss = *(const float4*)&ssin[ai];
    if (lane < 16) {
        q4.x = q4.x * cc.x - pq.x * ss.x;
        q4.y = q4.y * cc.y - pq.y * ss.y;
        q4.z = q4.z * cc.z - pq.z * ss.z;
        q4.w = q4.w * cc.w - pq.w * ss.w;
    } else {
        q4.x = q4.x * cc.x + pq.x * ss.x;
        q4.y = q4.y * cc.y + pq.y * ss.y;
        q4.z = q4.z * cc.z + pq.z * ss.z;
        q4.w = q4.w * cc.w + pq.w * ss.w;
    }

    const float4* k4 = (const float4*)kc;
    long base = ((long)p * 16 * 32 + h) * 32;
    float4 mn = make_float4(0, 0, 0, 0), mx = mn;
    float pm = -1e30f;

#pragma unroll
    for (int t = 0; t < 16; t++) {
        float4 kv = __ldg(&k4[base + (long)t * 1024 + lane]);
        if (t == 0) { mn = kv; mx = kv; }
        else {
            mn.x = fminf(mn.x, kv.x); mn.y = fminf(mn.y, kv.y);
            mn.z = fminf(mn.z, kv.z); mn.w = fminf(mn.w, kv.w);
            mx.x = fmaxf(mx.x, kv.x); mx.y = fmaxf(mx.y, kv.y);
            mx.z = fmaxf(mx.z, kv.z); mx.w = fmaxf(mx.w, kv.w);
        }
        float d = q4.x * kv.x + q4.y * kv.y + q4.z * kv.z + q4.w * kv.w;
#pragma unroll
        for (int o = 16; o > 0; o >>= 1) d += __shfl_xor_sync(0xffffffffu, d, o);
        d *= SCALE;
        pm = fmaxf(pm, d);
        if (lane == 0) g_sall[h * KVLEN + p * 16 + t] = d;
    }
    float e = fmaxf(q4.x * mn.x, q4.x * mx.x) + fmaxf(q4.y * mn.y, q4.y * mx.y)
            + fmaxf(q4.z * mn.z, q4.z * mx.z) + fmaxf(q4.w * mn.w, q4.w * mx.w);
#pragma unroll
    for (int o = 16; o > 0; o >>= 1) e += __shfl_xor_sync(0xffffffffu, e, o);
    if (lane == 0) {
        g_est[h * NPAGE + p]  = e;
        g_pmax[h * NPAGE + p] = pm;
    }
}

// ---------------- 2: top-256 select (radix) + softmax shift m ----------------
// 32 blocks (one per head) x 1024 threads
__global__ void __launch_bounds__(1024) k_sel() {
    int h = blockIdx.x, tid = threadIdx.x;
    int lane = tid & 31, wid = tid >> 5;
    __shared__ unsigned keys[NPAGE];    // 8 KB
    __shared__ int      cnt[256];
    __shared__ int      sel[TOPK];
    __shared__ float    wred[32];
    __shared__ unsigned sh_prefix;
    __shared__ int      sh_krem, sh_base;
    __shared__ float    sh_pm, sh_snew;

    // load est -> order-preserving uint keys; reduce per-page score max in-pass
    float pm = -1e30f;
    for (int i = tid; i < NPAGE; i += 1024) {
        unsigned u = __float_as_uint(g_est[h * NPAGE + i]);
        keys[i] = (u & 0x80000000u) ? ~u : (u | 0x80000000u);
        pm = fmaxf(pm, g_pmax[h * NPAGE + i]);
    }
    if (tid == 0) { sh_prefix = 0u; sh_krem = TOPK; sh_base = 0; }
    if (tid < 256) cnt[tid] = 0;
#pragma unroll
    for (int o = 16; o > 0; o >>= 1)
        pm = fmaxf(pm, __shfl_xor_sync(0xffffffffu, pm, o));
    if (lane == 0) wred[wid] = pm;
    __syncthreads();
    if (tid < 32) {
        float v = wred[tid];
#pragma unroll
        for (int o = 16; o > 0; o >>= 1)
            v = fmaxf(v, __shfl_xor_sync(0xffffffffu, v, o));
        if (tid == 0) sh_pm = v;
    }
    __syncthreads();

    // 4-round radix select: find T = 256th-largest key
#pragma unroll
    for (int shift = 24; shift >= 0; shift -= 8) {
        unsigned pmask = (shift == 24) ? 0u : (0xFFFFFFFFu << (shift + 8));
        unsigned pfx = sh_prefix;
        int krem = sh_krem;
        for (int i = tid; i < NPAGE; i += 1024)
            if ((keys[i] & pmask) == pfx)
                atomicAdd(&cnt[(keys[i] >> shift) & 255], 1);
        __syncthreads();
        // warp 0: suffix-inclusive sum over 256 bins (8 bins/lane + shfl scan)
        if (tid < 32) {
            int b0[8];
#pragma unroll
            for (int j = 0; j < 8; j++) b0[j] = cnt[tid * 8 + j];
#pragma unroll
            for (int j = 6; j >= 0; j--) b0[j] += b0[j + 1];
            int tot = b0[0], suf = tot;
#pragma unroll
            for (int off = 1; off < 32; off <<= 1) {
                int v = __shfl_down_sync(0xffffffffu, suf, off);
                if (tid + off < 32) suf += v;
            }
            int excl = suf - tot;
#pragma unroll
            for (int j = 0; j < 8; j++) cnt[tid * 8 + j] = b0[j] + excl;
        }
        __syncthreads();
        // exactly one bin d satisfies S[d+1] < krem <= S[d]
        if (tid < 256) {
            int S     = cnt[tid];
            int Snext = (tid < 255) ? cnt[tid + 1] : 0;
            if (Snext < krem && krem <= S) {
                sh_prefix = pfx | ((unsigned)tid << shift);
                sh_krem   = krem - Snext;
            }
        }
        __syncthreads();
        if (tid < 256) cnt[tid] = 0;   // reset for next round
        __syncthreads();
    }
    unsigned T = sh_prefix;

    // collect strictly-greater (all belong), then pad with ties (capped)
    for (int i = tid; i < NPAGE; i += 1024)
        if (keys[i] > T) sel[atomicAdd(&sh_base, 1)] = i;
    __syncthreads();
    for (int i = tid; i < NPAGE; i += 1024)
        if (keys[i] == T) {
            int p = atomicAdd(&sh_base, 1);
            if (p < TOPK) sel[p] = i;
        }
    __syncthreads();

    // s_new = (q . k_new) * SCALE from summed partials (RoPE dot-invariant)
    float vnew = 0.f;
    {
        float qv = 0.f, kv = 0.f;
        if (tid < 128) {
#pragma unroll
            for (int rg = 0; rg < 8; rg++) {
                qv   += g_qp[rg][h * DDIM + tid];
                kv   += g_kp[rg][h * DDIM + tid];
                vnew += g_vp[rg][h * DDIM + tid];
            }
        }
        float v = qv * kv;
#pragma unroll
        for (int o = 16; o > 0; o >>= 1) v += __shfl_xor_sync(0xffffffffu, v, o);
        if (lane == 0) wred[wid] = v;
        __syncthreads();
        if (tid == 0) sh_snew = (wred[0] + wred[1] + wred[2] + wred[3]) * SCALE;
        __syncthreads();
    }
    float s_new = sh_snew;
    float m     = fmaxf(sh_pm, s_new);   // >= true selected max: softmax-safe

    // emit pages, shift, Z seed, and unnormalized o init (new-token term)
    if (tid < TOPK) g_selp[h * TOPK + tid] = sel[tid];
    float en = expf(s_new - m);
    if (tid == 0) { g_m[h] = m; g_z[h] = en; }
    if (tid < 128)
        g_o[h * DDIM + tid] = en * vnew;
}

// ---------------- 3: weighted V gather + Z; also zeroes `out` ---------------
// grid = 32 heads * 32 chunks; 512 threads.  [R10 float2 body, measured 17.3us]
__global__ void __launch_bounds__(512) k_av(const float* __restrict__ vc,
                                            float* __restrict__ out) {
    int b = blockIdx.x;
    int h = b >> 5, ch = b & 31;
    int tid = threadIdx.x;
    int dim2 = tid & 63;        // float2 lane within the 128-dim row
    int part = tid >> 6;        // 0..7 token partition
    __shared__ float ws[128];
    __shared__ int   ti[128];
    __shared__ float sacc[1024];
    // fold `out` zeroing into the first 16 blocks (completes before k_out)
    if (b < 16 && tid < 256) out[b * 256 + tid] = 0.f;
    float m = g_m[h];
    if (tid < 128) {
        int page = g_selp[h * TOPK + ch * 8 + (tid >> 4)];
        int tok  = page * 16 + (tid & 15);
        ti[tid] = tok;
        ws[tid] = expf(g_sall[h * KVLEN + tok] - m);
    }
    __syncthreads();
    // Z partial: warp 0 sums the 128 weights, single atomic
    if (tid < 32) {
        float z = ws[tid] + ws[tid + 32] + ws[tid + 64] + ws[tid + 96];
#pragma unroll
        for (int o = 16; o > 0; o >>= 1) z += __shfl_xor_sync(0xffffffffu, z, o);
        if (tid == 0) atomicAdd(&g_z[h], z);
    }
    const float2* v2 = (const float2*)vc;
    float ax = 0.f, ay = 0.f;
#pragma unroll
    for (int t = 0; t < 16; t++) {
        int k = part * 16 + t;
        float w = ws[k];
        float2 vv = __ldg(&v2[((long)ti[k] * 32 + h) * 64 + dim2]);
        ax += w * vv.x; ay += w * vv.y;
    }
    sacc[part * 128 + dim2 * 2]     = ax;
    sacc[part * 128 + dim2 * 2 + 1] = ay;
    __syncthreads();
    if (tid < 128) {
        float s = 0.f;
#pragma unroll
        for (int p = 0; p < 8; p++) s += sacc[p * 128 + tid];
        atomicAdd(&g_o[h * DDIM + tid], s);
    }
}

// ---------------- 4: output GEMV; normalizes by 1/Z; resets g_qdone ----------
// grid = 32 colgroups * 32 rowgroups (one head each) = 1024 blocks, 128 thr
__global__ void k_out(const float* __restrict__ Wo, float* __restrict__ out) {
    if (blockIdx.x == 0 && threadIdx.x == 0) g_qdone = 0;  // for next replay
    int b  = blockIdx.x;
    int cg = b & 31;
    int h  = b >> 5;               // rowgroup == head (128 rows)
    int lane = threadIdx.x & 31;
    int wrp  = threadIdx.x >> 5;   // 4 warps, 32 rows each

    __shared__ float os[128];
    float zi = 1.f / g_z[h];
    os[threadIdx.x] = g_o[h * DDIM + threadIdx.x] * zi;
    __syncthreads();

    long i0  = (long)h * DDIM + wrp * 32;
    int col4 = cg * 32 + lane;
    const float4* W4 = (const float4*)Wo;
    float4 acc = make_float4(0.f, 0.f, 0.f, 0.f);
#pragma unroll 8
    for (int i = 0; i < 32; i++) {
        float  xv = os[wrp * 32 + i];
        float4 wv = __ldg(&W4[(i0 + i) * 1024 + col4]);
        acc.x += xv * wv.x; acc.y += xv * wv.y;
        acc.z += xv * wv.z; acc.w += xv * wv.w;
    }
    float* dst = &out[col4 * 4];
    atomicAdd(dst + 0, acc.x); atomicAdd(dst + 1, acc.y);
    atomicAdd(dst + 2, acc.z); atomicAdd(dst + 3, acc.w);
}

// ---------------- launch ------------------------------------------------------
extern "C" void kernel_launch(void* const* d_in, const int* in_sizes, int n_in,
                              void* d_out, int out_size) {
    const float* x  = (const float*)d_in[0];
    const float* kc = (const float*)d_in[1];
    const float* vc = (const float*)d_in[2];
    const float* Wq = (const float*)d_in[3];
    const float* Wk = (const float*)d_in[4];
    const float* Wv = (const float*)d_in[5];
    const float* Wo = (const float*)d_in[6];
    float* out = (float*)d_out;

    k_gemvscan<<<8960, 256>>>(kc, x, Wq, Wk, Wv);
    k_sel<<<32, 1024>>>();
    k_av<<<1024, 512>>>(vc, out);
    k_out<<<1024, 128>>>(Wo, out);
}

// round 16
// speedup vs baseline: 1.1920x; 1.1920x over previous
#include <cuda_runtime.h>
#include <math.h>

#define NHEAD 32
#define DDIM  128
#define KVLEN 32768
#define PAGE  16
#define NPAGE 2048
#define TOPK  256
#define NSEL  (TOPK * PAGE)          /* 4096 selected tokens per head */
#define HDIM  4096
#define SCALE 0.08838834764831845f   /* 1/sqrt(128) */

// ---------------- scratch (device globals; no allocations allowed) ----------
// Per-rowgroup GEMV partials: written with plain stores every run (no init).
__device__ float g_qp[8][HDIM];
__device__ float g_kp[8][HDIM];
__device__ float g_vp[8][HDIM];
__device__ float g_q[HDIM];              // final q, RoPE applied
__device__ float g_sall[NHEAD * KVLEN];  // all scores, scaled (4 MB)
__device__ float g_est[NHEAD * NPAGE];   // page estimates
__device__ float g_pmax[NHEAD * NPAGE];  // per-page score max (for softmax m)
__device__ int   g_selp[NHEAD * TOPK];   // selected page ids
__device__ float g_m[NHEAD];             // softmax shift (global score max)
__device__ float g_z[NHEAD];             // running Z (unnormalized)
__device__ float g_o[NHEAD * DDIM];      // UNNORMALIZED attention output
__device__ int   g_qdone = 0;            // #Q-GEMV blocks finished
__device__ int   g_qsum  = 0;            // q-finalize complete flag

// ---------------- 1: FUSED QKV GEMV + q-finalize + page scan -----------------
// blocks 0..767  : GEMV partials for Wq (0..255), Wk (256..511), Wv (512..767)
// block  768     : q-finalize (sum partials + RoPE); releases g_qsum
// blocks 769..8960: scan (8192 blocks = 2048 pages x 32 heads / 8 warps)
__global__ void __launch_bounds__(256) k_gemvscan(const float* __restrict__ kc,
                                                  const float* __restrict__ x,
                                                  const float* __restrict__ Wq,
                                                  const float* __restrict__ Wk,
                                                  const float* __restrict__ Wv) {
    if (blockIdx.x < 768) {
        int b  = blockIdx.x;
        int m  = b >> 8;           // 0 -> Wq, 1 -> Wk, 2 -> Wv
        int r  = b & 255;
        int cg = r & 31;
        int rg = r >> 5;
        const float* W = (m == 0) ? Wq : (m == 1) ? Wk : Wv;

        int lane = threadIdx.x & 31;
        int wrp  = threadIdx.x >> 5;   // 8 warps, 64 rows each

        __shared__ float xs[512];
        __shared__ float part[8][128];
        for (int i = threadIdx.x; i < 512; i += 256) xs[i] = x[rg * 512 + i];
        __syncthreads();

        int col4 = cg * 32 + lane;
        long i0  = (long)rg * 512 + wrp * 64;
        const float4* W4 = (const float4*)W;

        float4 acc = make_float4(0.f, 0.f, 0.f, 0.f);
#pragma unroll 8
        for (int i = 0; i < 64; i++) {
            float  xv = xs[wrp * 64 + i];
            float4 wv = __ldg(&W4[(i0 + i) * 1024 + col4]);
            acc.x += xv * wv.x; acc.y += xv * wv.y;
            acc.z += xv * wv.z; acc.w += xv * wv.w;
        }
        ((float4*)part[wrp])[lane] = acc;
        __syncthreads();
        if (wrp == 0) {
            float4 s = make_float4(0.f, 0.f, 0.f, 0.f);
#pragma unroll
            for (int w2 = 0; w2 < 8; w2++) {
                float4 p = ((float4*)part[w2])[lane];
                s.x += p.x; s.y += p.y; s.z += p.z; s.w += p.w;
            }
            float* dstbase = (m == 0) ? g_qp[rg] : (m == 1) ? g_kp[rg] : g_vp[rg];
            *(float4*)&dstbase[col4 * 4] = s;
        }
        if (m == 0) {
            __threadfence();
            __syncthreads();
            if (threadIdx.x == 0) atomicAdd(&g_qdone, 1);
        }
        return;
    }

    if (blockIdx.x == 768) {
        // ---- q-finalize: sum 8 partials + RoPE, once for the whole GPU ----
        __shared__ __align__(16) float scos[64], ssin[64];
        int tid = threadIdx.x;
        if (tid < 64) {
            float inv = (float)pow(10000.0, -(double)tid / 64.0);
            float ang = 32768.0f * inv;
            float s, c;
            sincosf(ang, &s, &c);
            scos[tid] = c;
            ssin[tid] = s;
        }
        if (tid == 0) {
            while (atomicAdd(&g_qdone, 0) < 256) __nanosleep(32);
        }
        __syncthreads();
        // 256 threads: head h = tid>>3, pairs (t&7)*8 .. +8
        int h  = tid >> 3;
        int p0 = (tid & 7) * 8;
#pragma unroll
        for (int j = 0; j < 8; j++) {
            int i = p0 + j;
            float a = 0.f, b2 = 0.f;
#pragma unroll
            for (int rg = 0; rg < 8; rg++) {
                a  += g_qp[rg][h * DDIM + i];
                b2 += g_qp[rg][h * DDIM + i + 64];
            }
            g_q[h * DDIM + i]      = a * scos[i] - b2 * ssin[i];
            g_q[h * DDIM + i + 64] = b2 * scos[i] + a * ssin[i];
        }
        __threadfence();
        __syncthreads();
        if (tid == 0) atomicExch(&g_qsum, 1);
        return;
    }

    // ---- scan: one warp per (page, head); no RoPE needed -----------------
    if (threadIdx.x == 0) {
        while (atomicAdd(&g_qsum, 0) == 0) __nanosleep(32);
    }
    __syncthreads();

    int g    = (blockIdx.x - 769) * 8 + (threadIdx.x >> 5);
    int lane = threadIdx.x & 31;
    int p = g >> 5, h = g & 31;

    float4 q4 = ((const float4*)g_q)[h * 32 + lane];

    const float4* k4 = (const float4*)kc;
    long base = ((long)p * 16 * 32 + h) * 32;
    float4 mn = make_float4(0, 0, 0, 0), mx = mn;
    float pm = -1e30f;

#pragma unroll
    for (int t = 0; t < 16; t++) {
        float4 kv = __ldg(&k4[base + (long)t * 1024 + lane]);
        if (t == 0) { mn = kv; mx = kv; }
        else {
            mn.x = fminf(mn.x, kv.x); mn.y = fminf(mn.y, kv.y);
            mn.z = fminf(mn.z, kv.z); mn.w = fminf(mn.w, kv.w);
            mx.x = fmaxf(mx.x, kv.x); mx.y = fmaxf(mx.y, kv.y);
            mx.z = fmaxf(mx.z, kv.z); mx.w = fmaxf(mx.w, kv.w);
        }
        float d = q4.x * kv.x + q4.y * kv.y + q4.z * kv.z + q4.w * kv.w;
#pragma unroll
        for (int o = 16; o > 0; o >>= 1) d += __shfl_xor_sync(0xffffffffu, d, o);
        d *= SCALE;
        pm = fmaxf(pm, d);
        if (lane == 0) g_sall[h * KVLEN + p * 16 + t] = d;
    }
    float e = fmaxf(q4.x * mn.x, q4.x * mx.x) + fmaxf(q4.y * mn.y, q4.y * mx.y)
            + fmaxf(q4.z * mn.z, q4.z * mx.z) + fmaxf(q4.w * mn.w, q4.w * mx.w);
#pragma unroll
    for (int o = 16; o > 0; o >>= 1) e += __shfl_xor_sync(0xffffffffu, e, o);
    if (lane == 0) {
        g_est[h * NPAGE + p]  = e;
        g_pmax[h * NPAGE + p] = pm;
    }
}

// ---------------- 2: top-256 select (radix) + softmax shift m ----------------
// 32 blocks (one per head) x 1024 threads  [R15 body, correctness-validated]
__global__ void __launch_bounds__(1024) k_sel() {
    int h = blockIdx.x, tid = threadIdx.x;
    int lane = tid & 31, wid = tid >> 5;
    __shared__ unsigned keys[NPAGE];    // 8 KB
    __shared__ int      cnt[256];
    __shared__ int      sel[TOPK];
    __shared__ float    wred[32];
    __shared__ unsigned sh_prefix;
    __shared__ int      sh_krem, sh_base;
    __shared__ float    sh_pm, sh_snew;

    float pm = -1e30f;
    for (int i = tid; i < NPAGE; i += 1024) {
        unsigned u = __float_as_uint(g_est[h * NPAGE + i]);
        keys[i] = (u & 0x80000000u) ? ~u : (u | 0x80000000u);
        pm = fmaxf(pm, g_pmax[h * NPAGE + i]);
    }
    if (tid == 0) { sh_prefix = 0u; sh_krem = TOPK; sh_base = 0; }
    if (tid < 256) cnt[tid] = 0;
#pragma unroll
    for (int o = 16; o > 0; o >>= 1)
        pm = fmaxf(pm, __shfl_xor_sync(0xffffffffu, pm, o));
    if (lane == 0) wred[wid] = pm;
    __syncthreads();
    if (tid < 32) {
        float v = wred[tid];
#pragma unroll
        for (int o = 16; o > 0; o >>= 1)
            v = fmaxf(v, __shfl_xor_sync(0xffffffffu, v, o));
        if (tid == 0) sh_pm = v;
    }
    __syncthreads();

#pragma unroll
    for (int shift = 24; shift >= 0; shift -= 8) {
        unsigned pmask = (shift == 24) ? 0u : (0xFFFFFFFFu << (shift + 8));
        unsigned pfx = sh_prefix;
        int krem = sh_krem;
        for (int i = tid; i < NPAGE; i += 1024)
            if ((keys[i] & pmask) == pfx)
                atomicAdd(&cnt[(keys[i] >> shift) & 255], 1);
        __syncthreads();
        if (tid < 32) {
            int b0[8];
#pragma unroll
            for (int j = 0; j < 8; j++) b0[j] = cnt[tid * 8 + j];
#pragma unroll
            for (int j = 6; j >= 0; j--) b0[j] += b0[j + 1];
            int tot = b0[0], suf = tot;
#pragma unroll
            for (int off = 1; off < 32; off <<= 1) {
                int v = __shfl_down_sync(0xffffffffu, suf, off);
                if (tid + off < 32) suf += v;
            }
            int excl = suf - tot;
#pragma unroll
            for (int j = 0; j < 8; j++) cnt[tid * 8 + j] = b0[j] + excl;
        }
        __syncthreads();
        if (tid < 256) {
            int S     = cnt[tid];
            int Snext = (tid < 255) ? cnt[tid + 1] : 0;
            if (Snext < krem && krem <= S) {
                sh_prefix = pfx | ((unsigned)tid << shift);
                sh_krem   = krem - Snext;
            }
        }
        __syncthreads();
        if (tid < 256) cnt[tid] = 0;
        __syncthreads();
    }
    unsigned T = sh_prefix;

    for (int i = tid; i < NPAGE; i += 1024)
        if (keys[i] > T) sel[atomicAdd(&sh_base, 1)] = i;
    __syncthreads();
    for (int i = tid; i < NPAGE; i += 1024)
        if (keys[i] == T) {
            int p = atomicAdd(&sh_base, 1);
            if (p < TOPK) sel[p] = i;
        }
    __syncthreads();

    // s_new = (q . k_new) * SCALE from RAW partial sums (RoPE dot-invariant)
    float vnew = 0.f;
    {
        float qv = 0.f, kv = 0.f;
        if (tid < 128) {
#pragma unroll
            for (int rg = 0; rg < 8; rg++) {
                qv   += g_qp[rg][h * DDIM + tid];
                kv   += g_kp[rg][h * DDIM + tid];
                vnew += g_vp[rg][h * DDIM + tid];
            }
        }
        float v = qv * kv;
#pragma unroll
        for (int o = 16; o > 0; o >>= 1) v += __shfl_xor_sync(0xffffffffu, v, o);
        if (lane == 0) wred[wid] = v;
        __syncthreads();
        if (tid == 0) sh_snew = (wred[0] + wred[1] + wred[2] + wred[3]) * SCALE;
        __syncthreads();
    }
    float s_new = sh_snew;
    float m     = fmaxf(sh_pm, s_new);

    if (tid < TOPK) g_selp[h * TOPK + tid] = sel[tid];
    float en = expf(s_new - m);
    if (tid == 0) { g_m[h] = m; g_z[h] = en; }
    if (tid < 128)
        g_o[h * DDIM + tid] = en * vnew;
}

// ---------------- 3: weighted V gather + Z; also zeroes `out` ---------------
// grid = 32 heads * 32 chunks; 512 threads.  [R10 float2 body, measured 17.3us]
__global__ void __launch_bounds__(512) k_av(const float* __restrict__ vc,
                                            float* __restrict__ out) {
    int b = blockIdx.x;
    int h = b >> 5, ch = b & 31;
    int tid = threadIdx.x;
    int dim2 = tid & 63;
    int part = tid >> 6;
    __shared__ float ws[128];
    __shared__ int   ti[128];
    __shared__ float sacc[1024];
    if (b < 16 && tid < 256) out[b * 256 + tid] = 0.f;
    float m = g_m[h];
    if (tid < 128) {
        int page = g_selp[h * TOPK + ch * 8 + (tid >> 4)];
        int tok  = page * 16 + (tid & 15);
        ti[tid] = tok;
        ws[tid] = expf(g_sall[h * KVLEN + tok] - m);
    }
    __syncthreads();
    if (tid < 32) {
        float z = ws[tid] + ws[tid + 32] + ws[tid + 64] + ws[tid + 96];
#pragma unroll
        for (int o = 16; o > 0; o >>= 1) z += __shfl_xor_sync(0xffffffffu, z, o);
        if (tid == 0) atomicAdd(&g_z[h], z);
    }
    const float2* v2 = (const float2*)vc;
    float ax = 0.f, ay = 0.f;
#pragma unroll
    for (int t = 0; t < 16; t++) {
        int k = part * 16 + t;
        float w = ws[k];
        float2 vv = __ldg(&v2[((long)ti[k] * 32 + h) * 64 + dim2]);
        ax += w * vv.x; ay += w * vv.y;
    }
    sacc[part * 128 + dim2 * 2]     = ax;
    sacc[part * 128 + dim2 * 2 + 1] = ay;
    __syncthreads();
    if (tid < 128) {
        float s = 0.f;
#pragma unroll
        for (int p = 0; p < 8; p++) s += sacc[p * 128 + tid];
        atomicAdd(&g_o[h * DDIM + tid], s);
    }
}

// ---------------- 4: output GEMV (256 thr, 8 warps); 1/Z; resets counters ----
// grid = 32 colgroups * 32 heads = 1024 blocks x 256 threads (8192 warps)
__global__ void __launch_bounds__(256) k_out(const float* __restrict__ Wo,
                                             float* __restrict__ out) {
    if (blockIdx.x == 0 && threadIdx.x == 0) { g_qdone = 0; g_qsum = 0; }
    int b  = blockIdx.x;
    int cg = b & 31;
    int h  = b >> 5;
    int tid = threadIdx.x;
    int lane = tid & 31, wrp = tid >> 5;   // 8 warps, 16 rows each

    __shared__ float os[128];
    __shared__ float4 sacc4[8][32];
    if (tid < 128) os[tid] = g_o[h * DDIM + tid] * (1.f / g_z[h]);
    __syncthreads();

    long i0  = (long)h * DDIM + wrp * 16;
    int col4 = cg * 32 + lane;
    const float4* W4 = (const float4*)Wo;
    float4 acc = make_float4(0.f, 0.f, 0.f, 0.f);
#pragma unroll
    for (int i = 0; i < 16; i++) {
        float  xv = os[wrp * 16 + i];
        float4 wv = __ldg(&W4[(i0 + i) * 1024 + col4]);
        acc.x += xv * wv.x; acc.y += xv * wv.y;
        acc.z += xv * wv.z; acc.w += xv * wv.w;
    }
    sacc4[wrp][lane] = acc;
    __syncthreads();
    if (tid < 32) {
        float4 s = make_float4(0.f, 0.f, 0.f, 0.f);
#pragma unroll
        for (int w2 = 0; w2 < 8; w2++) {
            float4 p = sacc4[w2][tid];
            s.x += p.x; s.y += p.y; s.z += p.z; s.w += p.w;
        }
        float* dst = &out[(cg * 32 + tid) * 4];
        atomicAdd(dst + 0, s.x); atomicAdd(dst + 1, s.y);
        atomicAdd(dst + 2, s.z); atomicAdd(dst + 3, s.w);
    }
}

// ---------------- launch ------------------------------------------------------
extern "C" void kernel_launch(void* const* d_in, const int* in_sizes, int n_in,
                              void* d_out, int out_size) {
    const float* x  = (const float*)d_in[0];
    const float* kc = (const float*)d_in[1];
    const float* vc = (const float*)d_in[2];
    const float* Wq = (const float*)d_in[3];
    const float* Wk = (const float*)d_in[4];
    const float* Wv = (const float*)d_in[5];
    const float* Wo = (const float*)d_in[6];
    float* out = (float*)d_out;

    k_gemvscan<<<8961, 256>>>(kc, x, Wq, Wk, Wv);
    k_sel<<<32, 1024>>>();
    k_av<<<1024, 512>>>(vc, out);
    k_out<<<1024, 256>>>(Wo, out);
}